// round 1
// baseline (speedup 1.0000x reference)
#include <cuda_runtime.h>
#include <cstdint>

#define N_NODES     500000
#define N_INC       2000000
#define N_HEDGES    100000
#define N_GRAPHS    512
#define CH          64
#define NPW         4   // nodes per warp in conv kernels

// ---------------- scratch (device globals; no allocation allowed) ----------------
__device__ float g_m [(long)N_HEDGES * CH];   // 25.6 MB
__device__ float g_m2[(long)N_HEDGES * CH];   // 25.6 MB
__device__ int   g_degN[N_NODES];
__device__ int   g_degE[N_HEDGES];
__device__ float g_binv[N_HEDGES];
__device__ float g_dinv[N_NODES];
__device__ int   g_rowptr[N_NODES + 1];
__device__ int   g_cursor[N_NODES];
__device__ int   g_csr[N_INC];
__device__ int   g_bsums[512];
__device__ float g_gsum[N_GRAPHS];
__device__ int   g_gcnt[N_GRAPHS];

// ---------------- zero scratch ----------------
__global__ void k_zero() {
    long t = (long)blockIdx.x * blockDim.x + threadIdx.x;
    long S = (long)gridDim.x * blockDim.x;
    float4 z4 = make_float4(0.f, 0.f, 0.f, 0.f);
    float4* m4 = (float4*)g_m;
    float4* n4 = (float4*)g_m2;
    const long M4 = (long)N_HEDGES * CH / 4;
    for (long j = t; j < M4; j += S) { m4[j] = z4; n4[j] = z4; }
    for (long j = t; j < N_NODES; j += S) { g_degN[j] = 0; g_cursor[j] = 0; }
    for (long j = t; j < N_HEDGES; j += S) g_degE[j] = 0;
    for (long j = t; j < N_GRAPHS; j += S) { g_gsum[j] = 0.f; g_gcnt[j] = 0; }
}

// ---------------- degree histograms ----------------
__global__ void k_hist(const int* __restrict__ row, const int* __restrict__ col) {
    int i = blockIdx.x * blockDim.x + threadIdx.x;
    if (i < N_INC) {
        atomicAdd(&g_degN[row[i]], 1);
        atomicAdd(&g_degE[col[i]], 1);
    }
}

// graph-size histogram (batch is sorted -> warp-aggregate)
__global__ void k_gcnt(const int* __restrict__ batch) {
    int i = blockIdx.x * blockDim.x + threadIdx.x;
    unsigned act = __ballot_sync(0xffffffffu, i < N_NODES);
    if (i < N_NODES) {
        int g = batch[i];
        unsigned mask = __match_any_sync(act, g);
        int leader = __ffs(mask) - 1;
        if ((threadIdx.x & 31) == leader) atomicAdd(&g_gcnt[g], __popc(mask));
    }
}

// ---------------- inverse degrees ----------------
__global__ void k_inv() {
    int i = blockIdx.x * blockDim.x + threadIdx.x;
    if (i < N_HEDGES) {
        int d = g_degE[i];
        g_binv[i] = d > 0 ? 1.f / (float)d : 0.f;
    }
    if (i < N_NODES) {
        int d = g_degN[i];
        g_dinv[i] = d > 0 ? 1.f / (float)d : 0.f;
    }
}

// ---------------- exclusive scan of g_degN -> g_rowptr ----------------
__global__ void k_scan1() {
    __shared__ int sh[1024];
    int tid = threadIdx.x;
    int i = blockIdx.x * 1024 + tid;
    int v = (i < N_NODES) ? g_degN[i] : 0;
    sh[tid] = v;
    __syncthreads();
#pragma unroll
    for (int off = 1; off < 1024; off <<= 1) {
        int t = (tid >= off) ? sh[tid - off] : 0;
        __syncthreads();
        sh[tid] += t;
        __syncthreads();
    }
    if (i < N_NODES) g_rowptr[i] = sh[tid] - v;   // exclusive (pre block-offset)
    if (tid == 1023) g_bsums[blockIdx.x] = sh[1023];
}

__global__ void k_scan2(int nblocks) {
    __shared__ int sh[512];
    int tid = threadIdx.x;
    int v = (tid < nblocks) ? g_bsums[tid] : 0;
    sh[tid] = v;
    __syncthreads();
#pragma unroll
    for (int off = 1; off < 512; off <<= 1) {
        int t = (tid >= off) ? sh[tid - off] : 0;
        __syncthreads();
        sh[tid] += t;
        __syncthreads();
    }
    if (tid < nblocks) g_bsums[tid] = sh[tid] - v;  // exclusive
}

__global__ void k_scan3() {
    int i = blockIdx.x * 1024 + threadIdx.x;
    if (i < N_NODES) g_rowptr[i] += g_bsums[blockIdx.x];
    if (i == 0) g_rowptr[N_NODES] = N_INC;
}

// ---------------- fill CSR (row-major adjacency: node -> hyperedges) ----------------
__global__ void k_fill(const int* __restrict__ row, const int* __restrict__ col) {
    int i = blockIdx.x * blockDim.x + threadIdx.x;
    if (i < N_INC) {
        int r = row[i];
        int pos = g_rowptr[r] + atomicAdd(&g_cursor[r], 1);
        g_csr[pos] = col[i];
    }
}

// ---------------- vec2 global red ----------------
__device__ __forceinline__ void red2(float* p, float a, float b) {
    asm volatile("red.global.add.v2.f32 [%0], {%1, %2};" :: "l"(p), "f"(a), "f"(b) : "memory");
}

// ---------------- conv1 pass A: t = xW1+b1 per node, scatter to m ----------------
__global__ void __launch_bounds__(256) k_conv_a(const float* __restrict__ x,
                                                const float* __restrict__ W,
                                                const float* __restrict__ b) {
    __shared__ __align__(16) float Ws[CH * CH];
    __shared__ float bs[CH];
    for (int i = threadIdx.x; i < CH * CH; i += 256) Ws[i] = W[i];
    if (threadIdx.x < CH) bs[threadIdx.x] = b[threadIdx.x];
    __syncthreads();

    int lane = threadIdx.x & 31;
    int warp = blockIdx.x * 8 + (threadIdx.x >> 5);
    int base = warp * NPW;
    if (base >= N_NODES) return;
    int c = lane * 2;

    float2 xv[NPW], t[NPW];
#pragma unroll
    for (int n = 0; n < NPW; n++) {
        int v = base + n;
        xv[n] = (v < N_NODES) ? *(const float2*)(x + (long)v * CH + c) : make_float2(0.f, 0.f);
        t[n] = make_float2(bs[c], bs[c + 1]);
    }
#pragma unroll
    for (int k = 0; k < CH; k++) {
        float2 w = *(const float2*)(Ws + k * CH + c);
#pragma unroll
        for (int n = 0; n < NPW; n++) {
            float xk = __shfl_sync(0xffffffffu, (k & 1) ? xv[n].y : xv[n].x, k >> 1);
            t[n].x += xk * w.x;
            t[n].y += xk * w.y;
        }
    }
#pragma unroll
    for (int n = 0; n < NPW; n++) {
        int v = base + n;
        if (v >= N_NODES) break;
        int beg = g_rowptr[v], end = g_rowptr[v + 1];
        for (int idx = beg; idx < end; idx++) {
            int e = g_csr[idx];
            red2(g_m + (long)e * CH + c, t[n].x, t[n].y);
        }
    }
}

// -------- conv1 pass B fused with conv2 pass A: gather m, relu, xW2+b2, scatter m2 --------
__global__ void __launch_bounds__(256) k_conv_b(const float* __restrict__ W,
                                                const float* __restrict__ b) {
    __shared__ __align__(16) float Ws[CH * CH];
    __shared__ float bs[CH];
    for (int i = threadIdx.x; i < CH * CH; i += 256) Ws[i] = W[i];
    if (threadIdx.x < CH) bs[threadIdx.x] = b[threadIdx.x];
    __syncthreads();

    int lane = threadIdx.x & 31;
    int warp = blockIdx.x * 8 + (threadIdx.x >> 5);
    int base = warp * NPW;
    if (base >= N_NODES) return;
    int c = lane * 2;

    float2 h[NPW], t[NPW];
#pragma unroll
    for (int n = 0; n < NPW; n++) {
        int v = base + n;
        float2 s = make_float2(0.f, 0.f);
        if (v < N_NODES) {
            int beg = g_rowptr[v], end = g_rowptr[v + 1];
            for (int idx = beg; idx < end; idx++) {
                int e = g_csr[idx];
                float bi = g_binv[e];
                float2 mv = *(const float2*)(g_m + (long)e * CH + c);
                s.x += bi * mv.x;
                s.y += bi * mv.y;
            }
            float di = g_dinv[v];
            h[n].x = fmaxf(di * s.x, 0.f);
            h[n].y = fmaxf(di * s.y, 0.f);
        } else {
            h[n] = make_float2(0.f, 0.f);
        }
        t[n] = make_float2(bs[c], bs[c + 1]);
    }
#pragma unroll
    for (int k = 0; k < CH; k++) {
        float2 w = *(const float2*)(Ws + k * CH + c);
#pragma unroll
        for (int n = 0; n < NPW; n++) {
            float xk = __shfl_sync(0xffffffffu, (k & 1) ? h[n].y : h[n].x, k >> 1);
            t[n].x += xk * w.x;
            t[n].y += xk * w.y;
        }
    }
#pragma unroll
    for (int n = 0; n < NPW; n++) {
        int v = base + n;
        if (v >= N_NODES) break;
        int beg = g_rowptr[v], end = g_rowptr[v + 1];
        for (int idx = beg; idx < end; idx++) {
            int e = g_csr[idx];
            red2(g_m2 + (long)e * CH + c, t[n].x, t[n].y);
        }
    }
}

// -------- conv2 pass B fused with pooling + fc dot: gather m2, relu, dot Wfc, aggregate --------
__global__ void __launch_bounds__(256) k_conv_c(const int* __restrict__ batch,
                                                const float* __restrict__ Wfc) {
    int lane = threadIdx.x & 31;
    int warp = blockIdx.x * 8 + (threadIdx.x >> 5);
    int base = warp * NPW;
    if (base >= N_NODES) return;
    int c = lane * 2;
    float wf0 = Wfc[c], wf1 = Wfc[c + 1];

    float acc = 0.f;
    int curg = -1;
#pragma unroll
    for (int n = 0; n < NPW; n++) {
        int v = base + n;
        if (v >= N_NODES) break;
        float2 s = make_float2(0.f, 0.f);
        int beg = g_rowptr[v], end = g_rowptr[v + 1];
        for (int idx = beg; idx < end; idx++) {
            int e = g_csr[idx];
            float bi = g_binv[e];
            float2 mv = *(const float2*)(g_m2 + (long)e * CH + c);
            s.x += bi * mv.x;
            s.y += bi * mv.y;
        }
        float di = g_dinv[v];
        float h0 = fmaxf(di * s.x, 0.f);
        float h1 = fmaxf(di * s.y, 0.f);
        float p = h0 * wf0 + h1 * wf1;
#pragma unroll
        for (int o = 16; o > 0; o >>= 1) p += __shfl_xor_sync(0xffffffffu, p, o);
        if (lane == 0) {
            int g = batch[v];
            if (g != curg) {
                if (curg >= 0) atomicAdd(&g_gsum[curg], acc);
                curg = g;
                acc = 0.f;
            }
            acc += p;
        }
    }
    if (lane == 0 && curg >= 0) atomicAdd(&g_gsum[curg], acc);
}

// ---------------- finalize ----------------
__global__ void k_fin(float* __restrict__ out, const float* __restrict__ bfc) {
    int g = blockIdx.x * blockDim.x + threadIdx.x;
    if (g < N_GRAPHS) {
        float cnt = fmaxf((float)g_gcnt[g], 1.f);
        out[g] = g_gsum[g] / cnt + bfc[0];
    }
}

// ---------------- launch ----------------
extern "C" void kernel_launch(void* const* d_in, const int* in_sizes, int n_in,
                              void* d_out, int out_size) {
    const float* x     = (const float*)d_in[0];
    const int*   eidx  = (const int*)d_in[1];
    const int*   row   = eidx;
    const int*   col   = eidx + N_INC;
    const int*   batch = (const int*)d_in[2];
    const float* W1    = (const float*)d_in[3];
    const float* b1    = (const float*)d_in[4];
    const float* W2    = (const float*)d_in[5];
    const float* b2    = (const float*)d_in[6];
    const float* Wfc   = (const float*)d_in[7];
    const float* bfc   = (const float*)d_in[8];
    float*       out   = (float*)d_out;

    const int NB_INC  = (N_INC + 255) / 256;      // 7813
    const int NB_NODE = (N_NODES + 255) / 256;    // 1954
    const int NB_SCAN = (N_NODES + 1023) / 1024;  // 489
    const int NB_CONV = ((N_NODES + NPW - 1) / NPW + 7) / 8;  // 15625

    k_zero<<<1024, 256>>>();
    k_hist<<<NB_INC, 256>>>(row, col);
    k_gcnt<<<NB_NODE, 256>>>(batch);
    k_inv<<<NB_NODE, 256>>>();
    k_scan1<<<NB_SCAN, 1024>>>();
    k_scan2<<<1, 512>>>(NB_SCAN);
    k_scan3<<<NB_SCAN, 1024>>>();
    k_fill<<<NB_INC, 256>>>(row, col);
    k_conv_a<<<NB_CONV, 256>>>(x, W1, b1);
    k_conv_b<<<NB_CONV, 256>>>(W2, b2);
    k_conv_c<<<NB_CONV, 256>>>(batch, Wfc);
    k_fin<<<2, 256>>>(out, bfc);
}